// round 9
// baseline (speedup 1.0000x reference)
#include <cuda_runtime.h>
#include <math.h>

#define TT    8192
#define HH    512
#define MM    4096
#define NENT  128
#define MAXD  600
#define NF    100
#define CAP   512

// ---------------- scratch ----------------
__device__ float2 g_emb[MAXD];
__device__ int    g_cnt[2 * NENT];      // zero at load; re-zeroed by k_pair tail
__device__ int    g_done;
__device__ float4 g_clist[NENT * CAP];  // (start_bits, sc0, sc1, 0); sorted by k_sort
__device__ float4 g_dlist[NENT * CAP];
__device__ float2 g_dpm[NENT * 32];     // inclusive prefix max of dis scores (sorted order)
__device__ float2 g_dsm[NENT * 32];     // inclusive suffix max

__device__ __forceinline__ int ldI(const void* p, int idx, int is64) {
    return is64 ? (int)((const long long*)p)[idx] : ((const int*)p)[idx];
}
__device__ __forceinline__ void fma2(unsigned long long& d, unsigned long long a,
                                     unsigned long long b) {
    asm("fma.rn.f32x2 %0, %1, %2, %0;" : "+l"(d) : "l"(a), "l"(b));
}
__device__ __forceinline__ void upk2(unsigned long long v, float& lo, float& hi) {
    asm("mov.b64 {%0, %1}, %2;" : "=f"(lo), "=f"(hi) : "l"(v));
}
__device__ __forceinline__ float tanh_fast(float x) {
    float y;
    asm("tanh.approx.f32 %0, %1;" : "=f"(y) : "f"(x));
    return y;
}

// ---------------- K1: fused span-sum + GEMM + tanh + Ws dot + bin (round-7) -------
#define BMM  64
#define BKK  32
#define NTH  320
#define ADP  130
#define WPAD 104
#define AS_F (BKK * ADP)
#define WT_F (BKK * WPAD)
#define EPI_F (64 * 50 * 2 + 64 * 10 * 2)
#define POOLF (AS_F + WT_F > EPI_F ? AS_F + WT_F : EPI_F)

__global__ __launch_bounds__(NTH, 1) void k_mention(
        const float* __restrict__ h,
        const void* __restrict__ csp, const void* __restrict__ cent,
        const void* __restrict__ dsp, const void* __restrict__ dent,
        const float* __restrict__ Wc, const float* __restrict__ bc,
        const float* __restrict__ Wd, const float* __restrict__ bd,
        const float* __restrict__ Ws,
        const float* __restrict__ Wemb) {
    __shared__ __align__(16) float pool[POOLF];
    __shared__ int ss[BMM], se[BMM], sent[BMM];
    __shared__ int s_is64;

    float* Asd = pool;
    float* Wt  = pool + AS_F;

    int tid = threadIdx.x;
    int m0 = blockIdx.x * BMM;
    bool isC = (m0 < MM);
    const float* W  = isC ? Wc : Wd;
    const float* bb = isC ? bc : bd;
    int wsb = isC ? 0 : NF;

    if (tid < 32) {
        unsigned v = (unsigned)((const int*)csp)[1 + 2 * tid];
        unsigned any = __ballot_sync(0xffffffffu, v != 0u);
        if (tid == 0) s_is64 = (any == 0u) ? 1 : 0;
    }
    __syncthreads();
    int is64 = s_is64;
    if (tid < BMM) {
        int mi = (m0 + tid) - (isC ? 0 : MM);
        const void* sp = isC ? csp : dsp;
        const void* en = isC ? cent : dent;
        ss[tid]   = ldI(sp, 2 * mi, is64);
        se[tid]   = ldI(sp, 2 * mi + 1, is64);
        sent[tid] = ldI(en, mi, is64);
    }
    __syncthreads();

    int kh = tid / 160;
    int t2 = tid - kh * 160;
    int rg = t2 & 15;
    int cg = t2 >> 4;
    int kh16 = kh * 16;

    const float4* __restrict__ hp = (const float4*)h;
    int r0 = tid >> 3, q0 = tid & 7;
    int n0 = se[r0] - ss[r0];
    const float4* p0 = hp + (size_t)ss[r0] * (HH / 4) + q0;
    int i1 = tid + NTH;
    bool has1 = (i1 < BMM * 8);
    int r1 = has1 ? (i1 >> 3) : 0, q1 = has1 ? (i1 & 7) : 0;
    int n1 = se[r1] - ss[r1];
    const float4* p1 = hp + (size_t)ss[r1] * (HH / 4) + q1;

    int kkp[5], c2p[5];
    #pragma unroll
    for (int p = 0; p < 5; p++) {
        int i = tid + NTH * p;
        kkp[p] = i / 50;
        c2p[p] = i - kkp[p] * 50;
    }

    unsigned long long acc[4][5];
    #pragma unroll
    for (int i = 0; i < 4; i++)
        #pragma unroll
        for (int j = 0; j < 5; j++) acc[i][j] = 0ull;

    float4 v0[8], v1[8];
    float2 wr[5];

    #pragma unroll
    for (int t = 0; t < 8; t++) v0[t] = __ldg(p0 + (size_t)min(t, n0) * (HH / 4));
    if (has1) {
        #pragma unroll
        for (int t = 0; t < 8; t++) v1[t] = __ldg(p1 + (size_t)min(t, n1) * (HH / 4));
    }
    #pragma unroll
    for (int p = 0; p < 5; p++)
        wr[p] = __ldg((const float2*)&W[(size_t)kkp[p] * NF + 2 * c2p[p]]);

    for (int tile = 0; tile < HH / BKK; tile++) {
        {
            float4 a = v0[0];
            #pragma unroll
            for (int t = 1; t < 8; t++)
                if (t <= n0) { a.x += v0[t].x; a.y += v0[t].y; a.z += v0[t].z; a.w += v0[t].w; }
            *(float2*)&Asd[(4 * q0 + 0) * ADP + 2 * r0] = make_float2(a.x, a.x);
            *(float2*)&Asd[(4 * q0 + 1) * ADP + 2 * r0] = make_float2(a.y, a.y);
            *(float2*)&Asd[(4 * q0 + 2) * ADP + 2 * r0] = make_float2(a.z, a.z);
            *(float2*)&Asd[(4 * q0 + 3) * ADP + 2 * r0] = make_float2(a.w, a.w);
            if (has1) {
                float4 b = v1[0];
                #pragma unroll
                for (int t = 1; t < 8; t++)
                    if (t <= n1) { b.x += v1[t].x; b.y += v1[t].y; b.z += v1[t].z; b.w += v1[t].w; }
                *(float2*)&Asd[(4 * q1 + 0) * ADP + 2 * r1] = make_float2(b.x, b.x);
                *(float2*)&Asd[(4 * q1 + 1) * ADP + 2 * r1] = make_float2(b.y, b.y);
                *(float2*)&Asd[(4 * q1 + 2) * ADP + 2 * r1] = make_float2(b.z, b.z);
                *(float2*)&Asd[(4 * q1 + 3) * ADP + 2 * r1] = make_float2(b.w, b.w);
            }
            #pragma unroll
            for (int p = 0; p < 5; p++)
                *(float2*)&Wt[kkp[p] * WPAD + 2 * c2p[p]] = wr[p];
        }
        __syncthreads();
        if (tile + 1 < HH / BKK) {
            int off = (tile + 1) * (BKK / 4);
            v0[0] = __ldg(p0 + off);
            #pragma unroll
            for (int t = 1; t < 8; t++)
                if (t <= n0) v0[t] = __ldg(p0 + off + (size_t)t * (HH / 4));
            if (has1) {
                v1[0] = __ldg(p1 + off);
                #pragma unroll
                for (int t = 1; t < 8; t++)
                    if (t <= n1) v1[t] = __ldg(p1 + off + (size_t)t * (HH / 4));
            }
            int kb = (tile + 1) * BKK * NF;
            #pragma unroll
            for (int p = 0; p < 5; p++)
                wr[p] = __ldg((const float2*)&W[kb + (size_t)kkp[p] * NF + 2 * c2p[p]]);
        }
        #pragma unroll
        for (int kki = 0; kki < 16; kki++) {
            int kk = kh16 + kki;
            const float* ab = &Asd[kk * ADP + 2 * rg];
            unsigned long long a0 = *(const unsigned long long*)(ab);
            unsigned long long a1 = *(const unsigned long long*)(ab + 32);
            unsigned long long a2 = *(const unsigned long long*)(ab + 64);
            unsigned long long a3 = *(const unsigned long long*)(ab + 96);
            #pragma unroll
            for (int j = 0; j < 5; j++) {
                unsigned long long w2 =
                    *(const unsigned long long*)&Wt[kk * WPAD + 2 * (cg + 10 * j)];
                fma2(acc[0][j], a0, w2);
                fma2(acc[1][j], a1, w2);
                fma2(acc[2][j], a2, w2);
                fma2(acc[3][j], a3, w2);
            }
        }
        __syncthreads();
    }

    float2* red  = (float2*)pool;
    float*  red2 = pool + 2 * 64 * 50;

    if (kh == 0) {
        #pragma unroll
        for (int i = 0; i < 4; i++)
            #pragma unroll
            for (int j = 0; j < 5; j++) {
                float lo, hi;
                upk2(acc[i][j], lo, hi);
                red[(rg + 16 * i) * 50 + (cg + 10 * j)] = make_float2(lo, hi);
            }
    }
    __syncthreads();
    if (kh == 1) {
        float s0[4] = {0.f, 0.f, 0.f, 0.f}, s1[4] = {0.f, 0.f, 0.f, 0.f};
        #pragma unroll
        for (int j = 0; j < 5; j++) {
            int p = cg + 10 * j, c0 = 2 * p;
            float2 bias = *(const float2*)&bb[c0];
            float2 w0 = *(const float2*)&Ws[(wsb + c0) * 2];
            float2 w1 = *(const float2*)&Ws[(wsb + c0 + 1) * 2];
            #pragma unroll
            for (int i = 0; i < 4; i++) {
                float lo, hi;
                upk2(acc[i][j], lo, hi);
                float2 o = red[(rg + 16 * i) * 50 + p];
                float t0 = tanh_fast(lo + o.x + bias.x);
                float t1 = tanh_fast(hi + o.y + bias.y);
                s0[i] += t0 * w0.x + t1 * w1.x;
                s1[i] += t0 * w0.y + t1 * w1.y;
            }
        }
        #pragma unroll
        for (int i = 0; i < 4; i++) {
            int r = rg + 16 * i;
            red2[(r * 10 + cg) * 2 + 0] = s0[i];
            red2[(r * 10 + cg) * 2 + 1] = s1[i];
        }
    }
    __syncthreads();
    if (tid < BMM) {
        float s0 = 0.f, s1 = 0.f;
        #pragma unroll
        for (int c = 0; c < 10; c++) {
            s0 += red2[(tid * 10 + c) * 2 + 0];
            s1 += red2[(tid * 10 + c) * 2 + 1];
        }
        int ent = sent[tid];
        int pos = atomicAdd(&g_cnt[(isC ? 0 : NENT) + ent], 1);
        if (pos < CAP) {
            float4 rec;
            rec.x = __int_as_float(ss[tid]);
            rec.y = s0; rec.z = s1; rec.w = 0.f;
            (isC ? g_clist : g_dlist)[ent * CAP + pos] = rec;
        }
    }

    if (blockIdx.x < 8) {
        for (int i = tid; i < 75 * 2; i += NTH) {
            int d = 75 * blockIdx.x + (i >> 1), k = i & 1;
            float a = 0.f;
            #pragma unroll
            for (int j = 0; j < 50; j++)
                a += Wemb[d * 50 + j] * Ws[(200 + j) * 2 + k];
            if (k == 0) g_emb[d].x = a; else g_emb[d].y = a;
        }
    }
}

// ---------------- K1.5: per-bin warp bitonic sort by start + prefix/suffix max ----
__global__ __launch_bounds__(256) void k_sort() {
    int gw = (blockIdx.x * blockDim.x + threadIdx.x) >> 5;
    int lane = threadIdx.x & 31;
    if (gw >= 2 * NENT) return;
    bool isD = (gw < NENT);
    int e = isD ? gw : gw - NENT;
    float4* list = isD ? &g_dlist[e * CAP] : &g_clist[e * CAP];
    int n = min(isD ? g_cnt[NENT + e] : g_cnt[e], CAP);
    if (n > 32) n = 32;                       // sort only head; tail handled in k_pair

    int key = 0x7FFFFFFF;
    float py = -INFINITY, pz = -INFINITY;
    if (lane < n) {
        float4 r = list[lane];
        key = __float_as_int(r.x);
        py = r.y; pz = r.z;
    }
    #pragma unroll
    for (int k = 2; k <= 32; k <<= 1) {
        #pragma unroll
        for (int j = k >> 1; j > 0; j >>= 1) {
            int   ok = __shfl_xor_sync(0xffffffffu, key, j);
            float oy = __shfl_xor_sync(0xffffffffu, py, j);
            float oz = __shfl_xor_sync(0xffffffffu, pz, j);
            bool up = ((lane & k) == 0);
            bool lower = ((lane & j) == 0);
            bool takeMin = (lower == up);
            bool takeOther = takeMin ? (ok < key) : (ok > key);
            if (takeOther) { key = ok; py = oy; pz = oz; }
        }
    }
    float pmy = py, pmz = pz, smy = py, smz = pz;
    #pragma unroll
    for (int off = 1; off < 32; off <<= 1) {
        float t;
        t = __shfl_up_sync(0xffffffffu, pmy, off);  if (lane >= off) pmy = fmaxf(pmy, t);
        t = __shfl_up_sync(0xffffffffu, pmz, off);  if (lane >= off) pmz = fmaxf(pmz, t);
        t = __shfl_down_sync(0xffffffffu, smy, off); if (lane + off < 32) smy = fmaxf(smy, t);
        t = __shfl_down_sync(0xffffffffu, smz, off); if (lane + off < 32) smz = fmaxf(smz, t);
    }
    list[lane] = make_float4(__int_as_float(key), py, pz, 0.f);
    if (isD) {
        g_dpm[e * 32 + lane] = make_float2(pmy, pmz);
        g_dsm[e * 32 + lane] = make_float2(smy, smz);
    }
}

// ---------------- K2: windowed pairwise max + fused softmax ----------------------
// FIXED lower_bound: 5 halving steps + final element check so result reaches 32.
__global__ __launch_bounds__(256) void k_pair(const float* __restrict__ bs,
                                              float* __restrict__ out) {
    __shared__ float2 s_emb[MAXD];
    __shared__ int    s_ds[16][32];
    __shared__ float2 s_yz[16][32];
    __shared__ float2 s_pm[16][32];
    __shared__ float2 s_sm[16][32];
    int ce = blockIdx.x;
    int dg = blockIdx.y;
    int tid = threadIdx.x;
    for (int i = tid; i < MAXD; i += 256) s_emb[i] = g_emb[i];
    for (int i = tid; i < 16 * 32; i += 256) {
        int dd = i >> 5, slot = i & 31;
        int de = dg * 16 + dd;
        float4 r = g_dlist[de * CAP + slot];
        s_ds[dd][slot] = __float_as_int(r.x);
        s_yz[dd][slot] = make_float2(r.y, r.z);
        s_pm[dd][slot] = g_dpm[de * 32 + slot];
        s_sm[dd][slot] = g_dsm[de * 32 + slot];
    }
    __syncthreads();

    int lane = tid & 31, w = tid >> 5;
    int nc = min(g_cnt[ce], CAP);
    float2 e599 = s_emb[MAXD - 1];
    float bs0 = __ldg(&bs[0]), bs1 = __ldg(&bs[1]);

    float M0[2] = {-INFINITY, -INFINITY};
    float M1[2] = {-INFINITY, -INFINITY};

    for (int c0 = 0; c0 < nc; c0 += 32) {
        int ci = c0 + lane;
        float4 cr = (ci < nc) ? g_clist[ce * CAP + ci]
                              : make_float4(0.f, -INFINITY, -INFINITY, 0.f);
        int cs = __float_as_int(cr.x);
        int t1 = cs - 598, tgt2 = cs + 599;

        #pragma unroll
        for (int dit = 0; dit < 2; dit++) {
            int dd = dit * 8 + w;
            // branchless lower_bound x2 over 32 sorted ints, range [0,32]
            int lo = 0, hi = 0;
            #pragma unroll
            for (int s = 16; s > 0; s >>= 1) {
                if (s_ds[dd][lo + s - 1] < t1)   lo += s;
                if (s_ds[dd][hi + s - 1] < tgt2) hi += s;
            }
            if (lo < 32 && s_ds[dd][lo] < t1)   lo += 1;   // final step: allow 32
            if (hi < 32 && s_ds[dd][hi] < tgt2) hi += 1;
            float lpx = (lo > 0)  ? s_pm[dd][lo - 1].x : -INFINITY;
            float lpy = (lo > 0)  ? s_pm[dd][lo - 1].y : -INFINITY;
            float rsx = (hi < 32) ? s_sm[dd][hi].x     : -INFINITY;
            float rsy = (hi < 32) ? s_sm[dd][hi].y     : -INFINITY;
            float mmx = fmaxf(lpx, rsx) + e599.x;      // clamped part, exact
            float mmy = fmaxf(lpy, rsy) + e599.y;
            for (int j = lo; j < hi; j++) {            // unclamped window
                int dsj = s_ds[dd][j];
                float2 yz = s_yz[dd][j];
                int d = abs(cs - dsj);                 // <= 598 by construction
                float2 ev = s_emb[d];
                mmx = fmaxf(mmx, yz.x + ev.x);
                mmy = fmaxf(mmy, yz.y + ev.y);
            }
            int de = dg * 16 + dd;
            int nd = min(g_cnt[NENT + de], CAP);
            for (int j = 32; j < nd; j++) {            // defensive tail (nd>32)
                float4 dr = g_dlist[de * CAP + j];
                int d = min(__usad((unsigned)cs, (unsigned)__float_as_int(dr.x), 0u),
                            (unsigned)(MAXD - 1));
                float2 ev = s_emb[d];
                mmx = fmaxf(mmx, dr.y + ev.x);
                mmy = fmaxf(mmy, dr.z + ev.y);
            }
            M0[dit] = fmaxf(M0[dit], cr.y + mmx);
            M1[dit] = fmaxf(M1[dit], cr.z + mmy);
        }
    }

    #pragma unroll
    for (int dit = 0; dit < 2; dit++) {
        float m0 = M0[dit], m1 = M1[dit];
        #pragma unroll
        for (int off = 16; off > 0; off >>= 1) {
            m0 = fmaxf(m0, __shfl_xor_sync(0xffffffffu, m0, off));
            m1 = fmaxf(m1, __shfl_xor_sync(0xffffffffu, m1, off));
        }
        if (lane == 0) {
            int de = dg * 16 + dit * 8 + w;
            float x0 = m0 + bs0, x1 = m1 + bs1;
            float mx = fmaxf(x0, x1);
            float e0 = expf(x0 - mx), e1 = expf(x1 - mx);
            float inv = 1.f / (e0 + e1);
            out[(ce * NENT + de) * 2 + 0] = e0 * inv;
            out[(ce * NENT + de) * 2 + 1] = e1 * inv;
        }
    }

    // ticket: last block re-zeroes g_cnt (+g_done) for next replay
    __threadfence();
    __syncthreads();
    if (tid == 0) {
        int old = atomicAdd(&g_done, 1);
        if (old == NENT * 8 - 1) {
            #pragma unroll 1
            for (int i = 0; i < 2 * NENT; i++) g_cnt[i] = 0;
            g_done = 0;
            __threadfence();
        }
    }
}

// ---------------- launch ----------------
extern "C" void kernel_launch(void* const* d_in, const int* in_sizes, int n_in,
                              void* d_out, int out_size) {
    const float* h    = (const float*)d_in[0];
    const void*  csp  = d_in[1];
    const void*  cent = d_in[2];
    const void*  dsp  = d_in[3];
    const void*  dent = d_in[4];
    const float* Wc   = (const float*)d_in[5];
    const float* bc   = (const float*)d_in[6];
    const float* Wd   = (const float*)d_in[7];
    const float* bd   = (const float*)d_in[8];
    const float* Wemb = (const float*)d_in[9];
    const float* Ws   = (const float*)d_in[10];
    const float* bs   = (const float*)d_in[11];
    float* out = (float*)d_out;

    k_mention<<<2 * MM / BMM, NTH>>>(h, csp, cent, dsp, dent, Wc, bc, Wd, bd, Ws, Wemb);
    k_sort<<<32, 256>>>();
    k_pair<<<dim3(NENT, 8), 256>>>(bs, out);
}